// round 2
// baseline (speedup 1.0000x reference)
#include <cuda_runtime.h>
#include <math.h>

#define NN 100000
#define NE 1600000

// Scratch (allocation-free): max row width 16 floats
__device__ __align__(16) float g_y[NN * 16];    // W_l-projected features (pre-aggregation)
__device__ __align__(16) float g_z[NN * 16];    // W_r-projected features + bias (root term)
__device__ __align__(16) float g_agg[NN * 16];  // scatter accumulator
__device__ __align__(16) float g_h[NN * 16];    // layer output
__device__ float g_deg[NN];

__device__ __forceinline__ float elu_f(float v) {
    return v > 0.0f ? v : expm1f(v);
}

// ---------------------------------------------------------------------------
// Transform: y = x @ Wl^T, z = x @ Wr^T + b; also zeros agg row (and deg).
// Weights transposed in smem -> float4 broadcast loads, float4 accumulators.
// ---------------------------------------------------------------------------
template <int IN, int OUT, bool ZERO_DEG>
__global__ void __launch_bounds__(256) transform_kernel(
    const float* __restrict__ x, const float* __restrict__ Wl,
    const float* __restrict__ Wr, const float* __restrict__ b,
    float* __restrict__ y, float* __restrict__ z,
    float* __restrict__ agg, float* __restrict__ deg)
{
    __shared__ __align__(16) float sWl[IN * OUT];  // transposed: [k][o]
    __shared__ __align__(16) float sWr[IN * OUT];
    __shared__ float sb[OUT];

    for (int i = threadIdx.x; i < IN * OUT; i += blockDim.x) {
        int o = i / IN;
        int k = i - o * IN;
        sWl[k * OUT + o] = Wl[i];
        sWr[k * OUT + o] = Wr[i];
    }
    if (threadIdx.x < OUT) sb[threadIdx.x] = b[threadIdx.x];
    __syncthreads();

    int node = blockIdx.x * blockDim.x + threadIdx.x;
    if (node >= NN) return;

    float xs[IN];
    const float4* xr = reinterpret_cast<const float4*>(x + (size_t)node * IN);
#pragma unroll
    for (int k4 = 0; k4 < IN / 4; k4++) {
        float4 v = xr[k4];
        xs[4 * k4 + 0] = v.x; xs[4 * k4 + 1] = v.y;
        xs[4 * k4 + 2] = v.z; xs[4 * k4 + 3] = v.w;
    }

    constexpr int O4 = OUT / 4;
    float4 aY[O4], aZ[O4];
#pragma unroll
    for (int j = 0; j < O4; j++) {
        aY[j] = make_float4(0.f, 0.f, 0.f, 0.f);
        aZ[j] = make_float4(0.f, 0.f, 0.f, 0.f);
    }

    const float4* wl4 = reinterpret_cast<const float4*>(sWl);
    const float4* wr4 = reinterpret_cast<const float4*>(sWr);
#pragma unroll 12
    for (int k = 0; k < IN; k++) {
        float xk = xs[k];
#pragma unroll
        for (int j = 0; j < O4; j++) {
            float4 wl = wl4[k * O4 + j];
            aY[j].x += xk * wl.x; aY[j].y += xk * wl.y;
            aY[j].z += xk * wl.z; aY[j].w += xk * wl.w;
            float4 wr = wr4[k * O4 + j];
            aZ[j].x += xk * wr.x; aZ[j].y += xk * wr.y;
            aZ[j].z += xk * wr.z; aZ[j].w += xk * wr.w;
        }
    }

    float4* yr = reinterpret_cast<float4*>(y + (size_t)node * OUT);
    float4* zr = reinterpret_cast<float4*>(z + (size_t)node * OUT);
    float4* ar = reinterpret_cast<float4*>(agg + (size_t)node * OUT);
#pragma unroll
    for (int j = 0; j < O4; j++) {
        yr[j] = aY[j];
        float4 zz = aZ[j];
        zz.x += sb[4 * j + 0]; zz.y += sb[4 * j + 1];
        zz.z += sb[4 * j + 2]; zz.w += sb[4 * j + 3];
        zr[j] = zz;
        ar[j] = make_float4(0.f, 0.f, 0.f, 0.f);
    }
    if (ZERO_DEG) deg[node] = 0.0f;
}

// ---------------------------------------------------------------------------
// Scatter: agg[dst] += y[src] via vector red.global (no return -> REDG path).
// Rows are 64B (OUT=16) / 32B (OUT=8), gathers hit L2 (y fits in 6.4MB).
// ---------------------------------------------------------------------------
template <int OUT, bool COUNT_DEG>
__global__ void __launch_bounds__(256) scatter_kernel(
    const int* __restrict__ src, const int* __restrict__ dst,
    const float* __restrict__ y, float* __restrict__ agg,
    float* __restrict__ deg)
{
    int e = blockIdx.x * blockDim.x + threadIdx.x;
    if (e >= NE) return;
    int s = __ldg(src + e);
    int d = __ldg(dst + e);
    const float4* yr = reinterpret_cast<const float4*>(y + (size_t)s * OUT);
    float* ap = agg + (size_t)d * OUT;
#pragma unroll
    for (int j = 0; j < OUT / 4; j++) {
        float4 v = yr[j];
        asm volatile("red.global.add.v4.f32 [%0], {%1, %2, %3, %4};"
                     :: "l"(ap + 4 * j), "f"(v.x), "f"(v.y), "f"(v.z), "f"(v.w)
                     : "memory");
    }
    if (COUNT_DEG) atomicAdd(deg + d, 1.0f);
}

// ---------------------------------------------------------------------------
// Finalize: h = ELU(agg / max(deg,1) + z); optional log_softmax epilogue.
// ---------------------------------------------------------------------------
template <int OUT, bool LOGSOFTMAX>
__global__ void __launch_bounds__(256) finalize_kernel(
    const float* __restrict__ agg, const float* __restrict__ z,
    const float* __restrict__ deg, float* __restrict__ h)
{
    int node = blockIdx.x * blockDim.x + threadIdx.x;
    if (node >= NN) return;
    float inv = 1.0f / fmaxf(deg[node], 1.0f);

    float v[OUT];
    const float4* ar = reinterpret_cast<const float4*>(agg + (size_t)node * OUT);
    const float4* zr = reinterpret_cast<const float4*>(z + (size_t)node * OUT);
#pragma unroll
    for (int j = 0; j < OUT / 4; j++) {
        float4 a = ar[j];
        float4 zz = zr[j];
        v[4 * j + 0] = elu_f(fmaf(a.x, inv, zz.x));
        v[4 * j + 1] = elu_f(fmaf(a.y, inv, zz.y));
        v[4 * j + 2] = elu_f(fmaf(a.z, inv, zz.z));
        v[4 * j + 3] = elu_f(fmaf(a.w, inv, zz.w));
    }

    float4* hr = reinterpret_cast<float4*>(h + (size_t)node * OUT);
    if (!LOGSOFTMAX) {
#pragma unroll
        for (int j = 0; j < OUT / 4; j++)
            hr[j] = make_float4(v[4 * j], v[4 * j + 1], v[4 * j + 2], v[4 * j + 3]);
    } else {
        float m = v[0];
#pragma unroll
        for (int c = 1; c < OUT; c++) m = fmaxf(m, v[c]);
        float s = 0.0f;
#pragma unroll
        for (int c = 0; c < OUT; c++) s += expf(v[c] - m);
        float ls = m + logf(s);
#pragma unroll
        for (int j = 0; j < OUT / 4; j++)
            hr[j] = make_float4(v[4 * j + 0] - ls, v[4 * j + 1] - ls,
                                v[4 * j + 2] - ls, v[4 * j + 3] - ls);
    }
}

extern "C" void kernel_launch(void* const* d_in, const int* in_sizes, int n_in,
                              void* d_out, int out_size)
{
    (void)in_sizes; (void)n_in; (void)out_size;

    const float* x   = (const float*)d_in[0];
    const int*   ei  = (const int*)d_in[1];   // int32: JAX x64-disabled downcasts int64
    const float* W1l = (const float*)d_in[2];
    const float* W1r = (const float*)d_in[3];
    const float* b1  = (const float*)d_in[4];
    const float* W2l = (const float*)d_in[5];
    const float* W2r = (const float*)d_in[6];
    const float* b2  = (const float*)d_in[7];
    const float* W3l = (const float*)d_in[8];
    const float* W3r = (const float*)d_in[9];
    const float* b3  = (const float*)d_in[10];
    float* out = (float*)d_out;

    const int* src = ei;            // edge_index[0]
    const int* dst = ei + NE;       // edge_index[1]

    float *py, *pz, *pagg, *ph, *pdeg;
    cudaGetSymbolAddress((void**)&py,   g_y);
    cudaGetSymbolAddress((void**)&pz,   g_z);
    cudaGetSymbolAddress((void**)&pagg, g_agg);
    cudaGetSymbolAddress((void**)&ph,   g_h);
    cudaGetSymbolAddress((void**)&pdeg, g_deg);

    const int nbN = (NN + 255) / 256;
    const int nbE = (NE + 255) / 256;

    // ---- Layer 1: 48 -> 16 ----
    transform_kernel<48, 16, true><<<nbN, 256>>>(x, W1l, W1r, b1, py, pz, pagg, pdeg);
    scatter_kernel<16, true><<<nbE, 256>>>(src, dst, py, pagg, pdeg);
    finalize_kernel<16, false><<<nbN, 256>>>(pagg, pz, pdeg, ph);

    // ---- Layer 2: 16 -> 16 ----
    transform_kernel<16, 16, false><<<nbN, 256>>>(ph, W2l, W2r, b2, py, pz, pagg, pdeg);
    scatter_kernel<16, false><<<nbE, 256>>>(src, dst, py, pagg, pdeg);
    finalize_kernel<16, false><<<nbN, 256>>>(pagg, pz, pdeg, ph);

    // ---- Layer 3: 16 -> 8 (+ log_softmax) ----
    transform_kernel<16, 8, false><<<nbN, 256>>>(ph, W3l, W3r, b3, py, pz, pagg, pdeg);
    scatter_kernel<8, false><<<nbE, 256>>>(src, dst, py, pagg, pdeg);
    finalize_kernel<8, true><<<nbN, 256>>>(pagg, pz, pdeg, out);
}

// round 3
// speedup vs baseline: 1.2930x; 1.2930x over previous
#include <cuda_runtime.h>
#include <math.h>

#define NN 100000
#define NE 1600000
#define SCAN_CHUNK 1024
#define NCHUNK ((NN + SCAN_CHUNK - 1) / SCAN_CHUNK)   // 98

// ---------------- scratch (allocation-free) ----------------
__device__ __align__(16) float g_y[NN * 16];   // W_l-projected features
__device__ __align__(16) float g_z[NN * 16];   // W_r-projected + bias
__device__ __align__(16) float g_h[NN * 16];   // layer output
__device__ int g_cnt[NN];                      // in-degree histogram
__device__ int g_off[NN + 1];                  // CSR row offsets
__device__ int g_cur[NN];                      // placement cursors
__device__ int g_csr[NE];                      // CSR src indices (grouped by dst)
__device__ int g_part[NCHUNK];                 // scan partials

__device__ __forceinline__ float elu_f(float v) {
    return v > 0.0f ? v : expm1f(v);
}

// ---------------------------------------------------------------------------
// CSR build: zero -> histogram -> 3-step scan -> place
// ---------------------------------------------------------------------------
__global__ void zero_cnt_kernel(int* __restrict__ cnt) {
    int i = blockIdx.x * blockDim.x + threadIdx.x;
    if (i < NN) cnt[i] = 0;
}

__global__ void hist_kernel(const int* __restrict__ dst, int* __restrict__ cnt) {
    int e = blockIdx.x * blockDim.x + threadIdx.x;
    if (e < NE) atomicAdd(cnt + __ldg(dst + e), 1);   // RED (no return)
}

__global__ void scan1_kernel(const int* __restrict__ cnt, int* __restrict__ part) {
    __shared__ int red[256];
    int b = blockIdx.x;
    int sum = 0;
    for (int i = threadIdx.x; i < SCAN_CHUNK; i += 256) {
        int idx = b * SCAN_CHUNK + i;
        if (idx < NN) sum += cnt[idx];
    }
    red[threadIdx.x] = sum;
    __syncthreads();
    for (int s = 128; s > 0; s >>= 1) {
        if (threadIdx.x < s) red[threadIdx.x] += red[threadIdx.x + s];
        __syncthreads();
    }
    if (threadIdx.x == 0) part[b] = red[0];
}

__global__ void scan2_kernel(int* __restrict__ part) {
    // tiny serial exclusive scan over NCHUNK partials
    if (threadIdx.x == 0 && blockIdx.x == 0) {
        int acc = 0;
        for (int i = 0; i < NCHUNK; i++) { int v = part[i]; part[i] = acc; acc += v; }
    }
}

__global__ void scan3_kernel(const int* __restrict__ cnt, const int* __restrict__ part,
                             int* __restrict__ off, int* __restrict__ cur) {
    __shared__ int wsum[8];
    int b = blockIdx.x, t = threadIdx.x;
    int gbase = b * SCAN_CHUNK + t * 4;
    int v0 = (gbase + 0 < NN) ? cnt[gbase + 0] : 0;
    int v1 = (gbase + 1 < NN) ? cnt[gbase + 1] : 0;
    int v2 = (gbase + 2 < NN) ? cnt[gbase + 2] : 0;
    int v3 = (gbase + 3 < NN) ? cnt[gbase + 3] : 0;
    int s = v0 + v1 + v2 + v3;

    int lane = t & 31, wid = t >> 5;
    int sc = s;
#pragma unroll
    for (int o = 1; o < 32; o <<= 1) {
        int n = __shfl_up_sync(0xffffffff, sc, o);
        if (lane >= o) sc += n;
    }
    if (lane == 31) wsum[wid] = sc;
    __syncthreads();
    if (wid == 0) {
        int ws = (lane < 8) ? wsum[lane] : 0;
#pragma unroll
        for (int o = 1; o < 8; o <<= 1) {
            int n = __shfl_up_sync(0xffffffff, ws, o);
            if (lane >= o) ws += n;
        }
        if (lane < 8) wsum[lane] = ws;   // inclusive warp sums
    }
    __syncthreads();

    int excl = sc - s + (wid > 0 ? wsum[wid - 1] : 0) + part[b];
    if (gbase + 0 < NN) { off[gbase + 0] = excl; cur[gbase + 0] = excl; } excl += v0;
    if (gbase + 1 < NN) { off[gbase + 1] = excl; cur[gbase + 1] = excl; } excl += v1;
    if (gbase + 2 < NN) { off[gbase + 2] = excl; cur[gbase + 2] = excl; } excl += v2;
    if (gbase + 3 < NN) { off[gbase + 3] = excl; cur[gbase + 3] = excl; }
    if (b == 0 && t == 0) off[NN] = NE;
}

__global__ void place_kernel(const int* __restrict__ src, const int* __restrict__ dst,
                             int* __restrict__ cur, int* __restrict__ csr) {
    int e = blockIdx.x * blockDim.x + threadIdx.x;
    if (e >= NE) return;
    int d = __ldg(dst + e);
    int p = atomicAdd(cur + d, 1);
    csr[p] = __ldg(src + e);
}

// ---------------------------------------------------------------------------
// Transform: gridDim.y selects pass: 0 -> y = x@Wl^T ; 1 -> z = x@Wr^T + b
// Weight transposed in smem; acc in regs; float4 I/O.
// ---------------------------------------------------------------------------
template <int IN, int OUT>
__global__ void __launch_bounds__(256) transform2_kernel(
    const float* __restrict__ x, const float* __restrict__ Wl,
    const float* __restrict__ Wr, const float* __restrict__ bias,
    float* __restrict__ y, float* __restrict__ z)
{
    __shared__ __align__(16) float sW[IN * OUT];   // [k][o]
    __shared__ float sb[OUT];
    const bool zpass = (blockIdx.y == 1);
    const float* W = zpass ? Wr : Wl;
    for (int i = threadIdx.x; i < IN * OUT; i += 256) {
        int o = i / IN, k = i - o * IN;
        sW[k * OUT + o] = W[i];
    }
    if (threadIdx.x < OUT) sb[threadIdx.x] = zpass ? bias[threadIdx.x] : 0.0f;
    __syncthreads();

    int node = blockIdx.x * 256 + threadIdx.x;
    if (node >= NN) return;

    float acc[OUT];
#pragma unroll
    for (int o = 0; o < OUT; o++) acc[o] = sb[o];

    const float4* xr = reinterpret_cast<const float4*>(x + (size_t)node * IN);
#pragma unroll
    for (int k4 = 0; k4 < IN / 4; k4++) {
        float4 xv = xr[k4];
#pragma unroll
        for (int o = 0; o < OUT; o++) {
            acc[o] = fmaf(xv.x, sW[(4 * k4 + 0) * OUT + o], acc[o]);
            acc[o] = fmaf(xv.y, sW[(4 * k4 + 1) * OUT + o], acc[o]);
            acc[o] = fmaf(xv.z, sW[(4 * k4 + 2) * OUT + o], acc[o]);
            acc[o] = fmaf(xv.w, sW[(4 * k4 + 3) * OUT + o], acc[o]);
        }
    }

    float* outp = zpass ? z : y;
    float4* orow = reinterpret_cast<float4*>(outp + (size_t)node * OUT);
#pragma unroll
    for (int j = 0; j < OUT / 4; j++)
        orow[j] = make_float4(acc[4 * j], acc[4 * j + 1], acc[4 * j + 2], acc[4 * j + 3]);
}

// ---------------------------------------------------------------------------
// Aggregate+finalize: OUT lanes per node; lane l owns feature l.
// Each edge -> one coalesced 64B (OUT=16) / 32B (OUT=8) row read from L2.
// h = ELU(mean + z); optional width-OUT log_softmax via shfl.
// ---------------------------------------------------------------------------
template <int OUT, bool LOGSOFTMAX>
__global__ void __launch_bounds__(256) aggregate_kernel(
    const int* __restrict__ off, const int* __restrict__ csr,
    const float* __restrict__ y, const float* __restrict__ z,
    float* __restrict__ h)
{
    int lane = threadIdx.x % OUT;
    int node = (blockIdx.x * blockDim.x + threadIdx.x) / OUT;
    if (node >= NN) return;

    int beg = __ldg(off + node);
    int end = __ldg(off + node + 1);

    float acc = 0.0f;
    int i = beg;
    for (; i + 4 <= end; i += 4) {
        int s0 = __ldg(csr + i + 0);
        int s1 = __ldg(csr + i + 1);
        int s2 = __ldg(csr + i + 2);
        int s3 = __ldg(csr + i + 3);
        float v0 = __ldg(y + (size_t)s0 * OUT + lane);
        float v1 = __ldg(y + (size_t)s1 * OUT + lane);
        float v2 = __ldg(y + (size_t)s2 * OUT + lane);
        float v3 = __ldg(y + (size_t)s3 * OUT + lane);
        acc += (v0 + v1) + (v2 + v3);
    }
    for (; i < end; i++)
        acc += __ldg(y + (size_t)__ldg(csr + i) * OUT + lane);

    float deg = (float)(end - beg);
    acc /= fmaxf(deg, 1.0f);
    acc += __ldg(z + (size_t)node * OUT + lane);
    float v = elu_f(acc);

    if (LOGSOFTMAX) {
        float m = v;
#pragma unroll
        for (int o = OUT / 2; o >= 1; o >>= 1)
            m = fmaxf(m, __shfl_xor_sync(0xffffffff, m, o, OUT));
        float ex = expf(v - m);
        float s = ex;
#pragma unroll
        for (int o = OUT / 2; o >= 1; o >>= 1)
            s += __shfl_xor_sync(0xffffffff, s, o, OUT);
        v = v - m - logf(s);
    }

    h[(size_t)node * OUT + lane] = v;
}

// ---------------------------------------------------------------------------
extern "C" void kernel_launch(void* const* d_in, const int* in_sizes, int n_in,
                              void* d_out, int out_size)
{
    (void)in_sizes; (void)n_in; (void)out_size;

    const float* x   = (const float*)d_in[0];
    const int*   ei  = (const int*)d_in[1];   // int32 (JAX x64-disabled)
    const float* W1l = (const float*)d_in[2];
    const float* W1r = (const float*)d_in[3];
    const float* b1  = (const float*)d_in[4];
    const float* W2l = (const float*)d_in[5];
    const float* W2r = (const float*)d_in[6];
    const float* b2  = (const float*)d_in[7];
    const float* W3l = (const float*)d_in[8];
    const float* W3r = (const float*)d_in[9];
    const float* b3  = (const float*)d_in[10];
    float* out = (float*)d_out;

    const int* src = ei;
    const int* dst = ei + NE;

    float *py, *pz, *ph;
    int *pcnt, *poff, *pcur, *pcsr, *ppart;
    cudaGetSymbolAddress((void**)&py,   g_y);
    cudaGetSymbolAddress((void**)&pz,   g_z);
    cudaGetSymbolAddress((void**)&ph,   g_h);
    cudaGetSymbolAddress((void**)&pcnt, g_cnt);
    cudaGetSymbolAddress((void**)&poff, g_off);
    cudaGetSymbolAddress((void**)&pcur, g_cur);
    cudaGetSymbolAddress((void**)&pcsr, g_csr);
    cudaGetSymbolAddress((void**)&ppart, g_part);

    const int nbN = (NN + 255) / 256;
    const int nbE = (NE + 255) / 256;

    // ---- CSR build (graph is reused by all 3 layers) ----
    zero_cnt_kernel<<<nbN, 256>>>(pcnt);
    hist_kernel<<<nbE, 256>>>(dst, pcnt);
    scan1_kernel<<<NCHUNK, 256>>>(pcnt, ppart);
    scan2_kernel<<<1, 32>>>(ppart);
    scan3_kernel<<<NCHUNK, 256>>>(pcnt, ppart, poff, pcur);
    place_kernel<<<nbE, 256>>>(src, dst, pcur, pcsr);

    // ---- Layer 1: 48 -> 16 ----
    transform2_kernel<48, 16><<<dim3(nbN, 2), 256>>>(x, W1l, W1r, b1, py, pz);
    aggregate_kernel<16, false><<<(NN * 16 + 255) / 256, 256>>>(poff, pcsr, py, pz, ph);

    // ---- Layer 2: 16 -> 16 ----
    transform2_kernel<16, 16><<<dim3(nbN, 2), 256>>>(ph, W2l, W2r, b2, py, pz);
    aggregate_kernel<16, false><<<(NN * 16 + 255) / 256, 256>>>(poff, pcsr, py, pz, ph);

    // ---- Layer 3: 16 -> 8 (+ log_softmax) ----
    transform2_kernel<16, 8><<<dim3(nbN, 2), 256>>>(ph, W3l, W3r, b3, py, pz);
    aggregate_kernel<8, true><<<(NN * 8 + 255) / 256, 256>>>(poff, pcsr, py, pz, out);
}